// round 13
// baseline (speedup 1.0000x reference)
#include <cuda_runtime.h>

#define EPSV   1e-5f
#define DW_THR 4.0f
#define PW_THR 0.001f

// Shapes: B=64, C=128, O=256, H=W=56, HW=3136
__device__ float g_y[64 * 128 * 3136];   // pruned depthwise output [B,C,HW]
__device__ int   g_keep[64 * 128];       // per-(b,c) keep flag
__device__ int   g_idx[64 * 128];        // per-b compacted kept-channel list
__device__ int   g_cnt[64];              // per-b kept count

// ---------------------------------------------------------------------------
// packed fp32x2 helpers (Blackwell FFMA2)
// ---------------------------------------------------------------------------
__device__ __forceinline__ unsigned long long fma2(unsigned long long a,
                                                   unsigned long long b,
                                                   unsigned long long c) {
    unsigned long long d;
    asm("fma.rn.f32x2 %0, %1, %2, %3;" : "=l"(d) : "l"(a), "l"(b), "l"(c));
    return d;
}
__device__ __forceinline__ unsigned long long mul2(unsigned long long a,
                                                   unsigned long long b) {
    unsigned long long d;
    asm("mul.rn.f32x2 %0, %1, %2;" : "=l"(d) : "l"(a), "l"(b));
    return d;
}
__device__ __forceinline__ unsigned long long pk2(float lo, float hi) {
    unsigned long long d;
    asm("mov.b64 %0, {%1, %2};" : "=l"(d) : "f"(lo), "f"(hi));
    return d;
}
__device__ __forceinline__ float2 upk2(unsigned long long v) {
    float2 r;
    asm("mov.b64 {%0, %1}, %2;" : "=f"(r.x), "=f"(r.y) : "l"(v));
    return r;
}

// ---------------------------------------------------------------------------
// Depthwise 3x3 + bias + BN1 + ReLU + per-(b,c) prune.
// 128 threads/block; 112 compute = 14 colgroups (4 cols) x 8 bands (7 rows).
// Per input row: 1 LDS.128 + 2 predicated scalars -> 5 column pairs reused by
// both output pairs. Per-lane FMA chain identical to all passing rounds.
// ---------------------------------------------------------------------------
__global__ __launch_bounds__(128) void dw_kernel(
    const float* __restrict__ x,
    const float* __restrict__ dw_w, const float* __restrict__ dw_b,
    const float* __restrict__ g1,  const float* __restrict__ b1,
    const float* __restrict__ m1,  const float* __restrict__ v1)
{
    __shared__ float sx[3136];
    __shared__ float red[4];
    __shared__ float s_bmax;

    const int slice = blockIdx.x;          // b*128 + c
    const int c = slice & 127;
    const float* xs = x + (size_t)slice * 3136;

    const unsigned long long ww0 = pk2(dw_w[c*9+0], dw_w[c*9+0]);
    const unsigned long long ww1 = pk2(dw_w[c*9+1], dw_w[c*9+1]);
    const unsigned long long ww2 = pk2(dw_w[c*9+2], dw_w[c*9+2]);
    const unsigned long long ww3 = pk2(dw_w[c*9+3], dw_w[c*9+3]);
    const unsigned long long ww4 = pk2(dw_w[c*9+4], dw_w[c*9+4]);
    const unsigned long long ww5 = pk2(dw_w[c*9+5], dw_w[c*9+5]);
    const unsigned long long ww6 = pk2(dw_w[c*9+6], dw_w[c*9+6]);
    const unsigned long long ww7 = pk2(dw_w[c*9+7], dw_w[c*9+7]);
    const unsigned long long ww8 = pk2(dw_w[c*9+8], dw_w[c*9+8]);
    const float s = g1[c] * rsqrtf(v1[c] + EPSV);
    const float t = fmaf(dw_b[c] - m1[c], s, b1[c]);
    const unsigned long long ss = pk2(s, s);
    const unsigned long long tt = pk2(t, t);

    const int tid = threadIdx.x;

    {   // stage slice: 784 coalesced float4
        const float4* x4 = (const float4*)xs;
        float4* s4 = (float4*)sx;
        for (int i = tid; i < 784; i += 128) s4[i] = x4[i];
    }
    __syncthreads();

    float4 lv[7];
    float mx = 0.f;
    int g = 0, band = 0;
    if (tid < 112) {
        g    = tid % 14;               // colgroup: cols 4g..4g+3
        band = tid / 14;               // 0..7 -> rows band*7..band*7+6
        const bool cL = (g > 0), cR = (g < 13);
        const int col = 4 * g;
        const int r0  = band * 7;

        // 5 column pairs per row: (c-1,c0)(c0,c1)(c1,c2)(c2,c3)(c3,c4)
        unsigned long long p0[5], p1[5];
        {   // row r0-1 (zero if band==0)
            if (r0 > 0) {
                int a = (r0 - 1) * 56 + col;
                float L = cL ? sx[a - 1] : 0.f;
                float4 A = *(const float4*)&sx[a];
                float R = cR ? sx[a + 4] : 0.f;
                p0[0] = pk2(L, A.x);   p0[1] = pk2(A.x, A.y);
                p0[2] = pk2(A.y, A.z); p0[3] = pk2(A.z, A.w);
                p0[4] = pk2(A.w, R);
            } else {
#pragma unroll
                for (int i = 0; i < 5; i++) p0[i] = 0ull;
            }
        }
        {   // row r0
            int a = r0 * 56 + col;
            float L = cL ? sx[a - 1] : 0.f;
            float4 A = *(const float4*)&sx[a];
            float R = cR ? sx[a + 4] : 0.f;
            p1[0] = pk2(L, A.x);   p1[1] = pk2(A.x, A.y);
            p1[2] = pk2(A.y, A.z); p1[3] = pk2(A.z, A.w);
            p1[4] = pk2(A.w, R);
        }

#pragma unroll
        for (int j = 0; j < 7; j++) {
            const int rr = r0 + j + 1;         // row below
            unsigned long long p2[5];
            if (rr < 56) {
                int a = rr * 56 + col;
                float L = cL ? sx[a - 1] : 0.f;
                float4 A = *(const float4*)&sx[a];
                float R = cR ? sx[a + 4] : 0.f;
                p2[0] = pk2(L, A.x);   p2[1] = pk2(A.x, A.y);
                p2[2] = pk2(A.y, A.z); p2[3] = pk2(A.z, A.w);
                p2[4] = pk2(A.w, R);
            } else {
#pragma unroll
                for (int i = 0; i < 5; i++) p2[i] = 0ull;
            }

            // P0 = outputs (c0,c1): pairs [0],[1],[2] per window row
            unsigned long long a0 = mul2(p0[0], ww0);
            a0 = fma2(p0[1], ww1, a0); a0 = fma2(p0[2], ww2, a0);
            a0 = fma2(p1[0], ww3, a0); a0 = fma2(p1[1], ww4, a0);
            a0 = fma2(p1[2], ww5, a0);
            a0 = fma2(p2[0], ww6, a0); a0 = fma2(p2[1], ww7, a0);
            a0 = fma2(p2[2], ww8, a0);
            a0 = fma2(a0, ss, tt);
            // P1 = outputs (c2,c3): pairs [2],[3],[4]
            unsigned long long a1 = mul2(p0[2], ww0);
            a1 = fma2(p0[3], ww1, a1); a1 = fma2(p0[4], ww2, a1);
            a1 = fma2(p1[2], ww3, a1); a1 = fma2(p1[3], ww4, a1);
            a1 = fma2(p1[4], ww5, a1);
            a1 = fma2(p2[2], ww6, a1); a1 = fma2(p2[3], ww7, a1);
            a1 = fma2(p2[4], ww8, a1);
            a1 = fma2(a1, ss, tt);

            float2 q0 = upk2(a0), q1 = upk2(a1);
            float z0 = fmaxf(q0.x, 0.f), z1 = fmaxf(q0.y, 0.f);
            float z2 = fmaxf(q1.x, 0.f), z3 = fmaxf(q1.y, 0.f);
            lv[j] = make_float4(z0, z1, z2, z3);
            mx = fmaxf(mx, fmaxf(fmaxf(z0, z1), fmaxf(z2, z3)));

#pragma unroll
            for (int i = 0; i < 5; i++) { p0[i] = p1[i]; p1[i] = p2[i]; }
        }
    }

    for (int off = 16; off; off >>= 1)
        mx = fmaxf(mx, __shfl_xor_sync(0xffffffffu, mx, off));
    if ((tid & 31) == 0) red[tid >> 5] = mx;
    __syncthreads();
    if (tid == 0) {
        float m = fmaxf(fmaxf(red[0], red[1]), fmaxf(red[2], red[3]));
        s_bmax = m;
        g_keep[slice] = (m >= DW_THR) ? 1 : 0;
    }
    __syncthreads();

    if (s_bmax >= DW_THR && tid < 112) {
        float* yo = g_y + (size_t)slice * 3136 + band * 7 * 56 + 4 * g;
#pragma unroll
        for (int j = 0; j < 7; j++)
            *(float4*)(yo + j * 56) = lv[j];
    }
}

// ---------------------------------------------------------------------------
// Per-batch compaction of kept channels
// ---------------------------------------------------------------------------
__global__ void compact_kernel() {
    const int b = blockIdx.x;
    const int tid = threadIdx.x;              // 128 threads
    __shared__ int wcnt[4];
    const int f = g_keep[b * 128 + tid];
    const unsigned bal = __ballot_sync(0xffffffffu, f);
    const int lane = tid & 31, w = tid >> 5;
    const int pre = __popc(bal & ((1u << lane) - 1u));
    if (lane == 0) wcnt[w] = __popc(bal);
    __syncthreads();
    int off = 0;
#pragma unroll
    for (int i = 0; i < 4; i++) if (i < w) off += wcnt[i];
    if (f) g_idx[b * 128 + off + pre] = tid;
    if (tid == 0) g_cnt[b] = wcnt[0] + wcnt[1] + wcnt[2] + wcnt[3];
}

// ---------------------------------------------------------------------------
// Pointwise conv + BN2 + ReLU + BLOCK-LOCAL prune. (round-12 structure)
// Block = 32 O x 3136 HW stripe. grid (8, 64) = 512 blocks, 256 threads.
// ---------------------------------------------------------------------------
#define KSUB 32
__global__ __launch_bounds__(256, 4) void pw_kernel(
    const float* __restrict__ pw_w, const float* __restrict__ pw_b,
    const float* __restrict__ g2,  const float* __restrict__ b2,
    const float* __restrict__ m2,  const float* __restrict__ v2,
    float* __restrict__ out)
{
    __shared__ float sWs[KSUB][36];          // [k][o]  32 used + 4 pad
    __shared__ float sYs[KSUB][132];         // [k][hw] 128 used + 4 pad
    __shared__ int   sidx[128];
    __shared__ unsigned char sfail[32];

    const int tid = threadIdx.x;
    const int tx = tid & 31;                 // hw: 32 lanes x 4 floats
    const int ty = tid >> 5;                 // o : 8 warps x 4 o's
    const int ob = blockIdx.x * 32;
    const int b  = blockIdx.y;

    const int cnt  = g_cnt[b];
    const int cnt4 = (cnt + 3) & ~3;
    const int nsub = (cnt4 + KSUB - 1) / KSUB;

    if (tid < 128) sidx[tid] = (tid < cnt) ? g_idx[b * 128 + tid] : -1;
    __syncthreads();

    float sc[4], tc[4], m[4];
    float* orow[4];
#pragma unroll
    for (int r = 0; r < 4; r++) {
        int o = ob + ty * 4 + r;
        sc[r] = g2[o] * rsqrtf(v2[o] + EPSV);
        tc[r] = fmaf(pw_b[o] - m2[o], sc[r], b2[o]);
        m[r] = 0.f;
        orow[r] = out + ((size_t)(b * 256 + o)) * 3136;
    }

    for (int it = 0; it < 25; it++) {
        const int hw0 = it * 128;
        const bool full = (it < 24);
        const bool live = full | (tx < 16);

        unsigned long long acc[2][4];
#pragma unroll
        for (int p = 0; p < 2; p++)
#pragma unroll
            for (int q = 0; q < 4; q++) acc[p][q] = 0ull;

        for (int kt = 0; kt < nsub; kt++) {
            const int kbase = kt * KSUB;
            int klim = cnt4 - kbase;
            if (klim > KSUB) klim = KSUB;

            for (int i = tid; i < klim * 32; i += 256) {
                int lk = i >> 5, oo = i & 31;
                int ch = sidx[kbase + lk];
                sWs[lk][oo] = (ch >= 0) ? pw_w[(ob + oo) * 128 + ch] : 0.f;
            }
            if (full) {
                for (int i = tid; i < klim * 32; i += 256) {
                    int lk = i >> 5, f4 = i & 31;
                    int ch = sidx[kbase + lk];
                    float4 v = make_float4(0.f, 0.f, 0.f, 0.f);
                    if (ch >= 0)
                        v = *(const float4*)(g_y + ((size_t)(b * 128 + ch)) * 3136 + hw0 + f4 * 4);
                    *(float4*)&sYs[lk][f4 * 4] = v;
                }
            } else {
                for (int i = tid; i < klim * 16; i += 256) {
                    int lk = i >> 4, f4 = i & 15;
                    int ch = sidx[kbase + lk];
                    float4 v = make_float4(0.f, 0.f, 0.f, 0.f);
                    if (ch >= 0)
                        v = *(const float4*)(g_y + ((size_t)(b * 128 + ch)) * 3136 + hw0 + f4 * 4);
                    *(float4*)&sYs[lk][f4 * 4] = v;
                }
            }
            __syncthreads();

            if (live) {
                for (int lk0 = 0; lk0 < klim; lk0 += 4) {
#pragma unroll
                    for (int ku = 0; ku < 4; ku++) {
                        int lk = lk0 + ku;
                        float4 Y = *(const float4*)&sYs[lk][tx * 4];
                        float4 Wv = *(const float4*)&sWs[lk][ty * 4];
                        unsigned long long w01 = pk2(Wv.x, Wv.y);
                        unsigned long long w23 = pk2(Wv.z, Wv.w);
                        unsigned long long yx = pk2(Y.x, Y.x), yy = pk2(Y.y, Y.y);
                        unsigned long long yz = pk2(Y.z, Y.z), yw = pk2(Y.w, Y.w);
                        acc[0][0] = fma2(w01, yx, acc[0][0]);
                        acc[0][1] = fma2(w01, yy, acc[0][1]);
                        acc[0][2] = fma2(w01, yz, acc[0][2]);
                        acc[0][3] = fma2(w01, yw, acc[0][3]);
                        acc[1][0] = fma2(w23, yx, acc[1][0]);
                        acc[1][1] = fma2(w23, yy, acc[1][1]);
                        acc[1][2] = fma2(w23, yz, acc[1][2]);
                        acc[1][3] = fma2(w23, yw, acc[1][3]);
                    }
                }
            }
            __syncthreads();
        }

        if (live) {
            float z[4][4];
#pragma unroll
            for (int q = 0; q < 4; q++) {
                float2 a01 = upk2(acc[0][q]);
                float2 a23 = upk2(acc[1][q]);
                z[0][q] = fmaxf(fmaf(a01.x, sc[0], tc[0]), 0.f);
                z[1][q] = fmaxf(fmaf(a01.y, sc[1], tc[1]), 0.f);
                z[2][q] = fmaxf(fmaf(a23.x, sc[2], tc[2]), 0.f);
                z[3][q] = fmaxf(fmaf(a23.y, sc[3], tc[3]), 0.f);
            }
#pragma unroll
            for (int r = 0; r < 4; r++) {
                m[r] = fmaxf(m[r], fmaxf(fmaxf(z[r][0], z[r][1]),
                                         fmaxf(z[r][2], z[r][3])));
                *(float4*)(orow[r] + hw0 + tx * 4) =
                    make_float4(z[r][0], z[r][1], z[r][2], z[r][3]);
            }
        }
    }

#pragma unroll
    for (int r = 0; r < 4; r++) {
#pragma unroll
        for (int off = 1; off < 32; off <<= 1)
            m[r] = fmaxf(m[r], __shfl_xor_sync(0xffffffffu, m[r], off));
    }
    if (tx == 0) {
#pragma unroll
        for (int r = 0; r < 4; r++)
            sfail[ty * 4 + r] = (m[r] < PW_THR) ? 1 : 0;
    }
    __syncthreads();

    const float4 zz = make_float4(0.f, 0.f, 0.f, 0.f);
    for (int oo = 0; oo < 32; oo++) {
        if (sfail[oo]) {
            float4* p4 = (float4*)(out + ((size_t)(b * 256 + ob + oo)) * 3136);
            for (int i = tid; i < 784; i += 256) p4[i] = zz;
        }
    }
}

// ---------------------------------------------------------------------------
extern "C" void kernel_launch(void* const* d_in, const int* in_sizes, int n_in,
                              void* d_out, int out_size)
{
    const float* x    = (const float*)d_in[0];
    const float* dw_w = (const float*)d_in[1];
    const float* dw_b = (const float*)d_in[2];
    const float* g1   = (const float*)d_in[3];
    const float* b1   = (const float*)d_in[4];
    const float* m1   = (const float*)d_in[5];
    const float* v1   = (const float*)d_in[6];
    const float* pw_w = (const float*)d_in[7];
    const float* pw_b = (const float*)d_in[8];
    const float* g2   = (const float*)d_in[9];
    const float* b2   = (const float*)d_in[10];
    const float* m2   = (const float*)d_in[11];
    const float* v2   = (const float*)d_in[12];
    float* out = (float*)d_out;

    dw_kernel<<<64 * 128, 128>>>(x, dw_w, dw_b, g1, b1, m1, v1);
    compact_kernel<<<64, 128>>>();
    pw_kernel<<<dim3(8, 64), 256>>>(pw_w, pw_b, g2, b2, m2, v2, out);
}

// round 14
// speedup vs baseline: 1.1240x; 1.1240x over previous
#include <cuda_runtime.h>

#define EPSV   1e-5f
#define DW_THR 4.0f
#define PW_THR 0.001f

// Shapes: B=64, C=128, O=256, H=W=56, HW=3136
__device__ float g_y[64 * 128 * 3136];   // pruned depthwise output [B,C,HW]
__device__ int   g_keep[64 * 128];       // per-(b,c) keep flag
__device__ int   g_idx[64 * 128];        // per-b compacted kept-channel list
__device__ int   g_cnt[64];              // per-b kept count

// ---------------------------------------------------------------------------
// packed fp32x2 helpers (Blackwell FFMA2)
// ---------------------------------------------------------------------------
__device__ __forceinline__ unsigned long long fma2(unsigned long long a,
                                                   unsigned long long b,
                                                   unsigned long long c) {
    unsigned long long d;
    asm("fma.rn.f32x2 %0, %1, %2, %3;" : "=l"(d) : "l"(a), "l"(b), "l"(c));
    return d;
}
__device__ __forceinline__ unsigned long long mul2(unsigned long long a,
                                                   unsigned long long b) {
    unsigned long long d;
    asm("mul.rn.f32x2 %0, %1, %2;" : "=l"(d) : "l"(a), "l"(b));
    return d;
}
__device__ __forceinline__ unsigned long long pk2(float lo, float hi) {
    unsigned long long d;
    asm("mov.b64 %0, {%1, %2};" : "=l"(d) : "f"(lo), "f"(hi));
    return d;
}
__device__ __forceinline__ float2 upk2(unsigned long long v) {
    float2 r;
    asm("mov.b64 {%0, %1}, %2;" : "=f"(r.x), "=f"(r.y) : "l"(v));
    return r;
}

// ---------------------------------------------------------------------------
// Depthwise 3x3 + bias + BN1 + ReLU + per-(b,c) prune.
// ROUND-12 VERSION (measured 38.2us, occ 93%): 256 threads, FFMA2 col pairs,
// 224 compute = 28 col-pairs x 8 bands x 7 rows.
// ---------------------------------------------------------------------------
__global__ __launch_bounds__(256) void dw_kernel(
    const float* __restrict__ x,
    const float* __restrict__ dw_w, const float* __restrict__ dw_b,
    const float* __restrict__ g1,  const float* __restrict__ b1,
    const float* __restrict__ m1,  const float* __restrict__ v1)
{
    __shared__ float sx[3136];
    __shared__ float red[8];
    __shared__ float s_bmax;

    const int slice = blockIdx.x;          // b*128 + c
    const int c = slice & 127;
    const float* xs = x + (size_t)slice * 3136;

    const unsigned long long ww0 = pk2(dw_w[c*9+0], dw_w[c*9+0]);
    const unsigned long long ww1 = pk2(dw_w[c*9+1], dw_w[c*9+1]);
    const unsigned long long ww2 = pk2(dw_w[c*9+2], dw_w[c*9+2]);
    const unsigned long long ww3 = pk2(dw_w[c*9+3], dw_w[c*9+3]);
    const unsigned long long ww4 = pk2(dw_w[c*9+4], dw_w[c*9+4]);
    const unsigned long long ww5 = pk2(dw_w[c*9+5], dw_w[c*9+5]);
    const unsigned long long ww6 = pk2(dw_w[c*9+6], dw_w[c*9+6]);
    const unsigned long long ww7 = pk2(dw_w[c*9+7], dw_w[c*9+7]);
    const unsigned long long ww8 = pk2(dw_w[c*9+8], dw_w[c*9+8]);
    const float s = g1[c] * rsqrtf(v1[c] + EPSV);
    const float t = fmaf(dw_b[c] - m1[c], s, b1[c]);
    const unsigned long long ss = pk2(s, s);
    const unsigned long long tt = pk2(t, t);

    const int tid = threadIdx.x;

    {   // stage slice: 784 coalesced float4
        const float4* x4 = (const float4*)xs;
        float4* s4 = (float4*)sx;
        for (int i = tid; i < 784; i += 256) s4[i] = x4[i];
    }
    __syncthreads();

    float2 lv[7];
    float mx = 0.f;
    int p = 0, band = 0;
    if (tid < 224) {
        band = tid / 28;               // 0..7
        p    = tid - band * 28;        // col pair -> cols 2p, 2p+1
        const bool cL = (p > 0), cR = (p < 27);
        const int col = 2 * p;
        const int r0  = band * 7;

        unsigned long long r0q0, r0q1, r0q2, r1q0, r1q1, r1q2;
        {
            float c0 = 0.f, c1 = 0.f, c2 = 0.f, c3 = 0.f;
            if (r0 > 0) {
                int a = (r0 - 1) * 56 + col;
                c0 = cL ? sx[a - 1] : 0.f;
                c1 = sx[a]; c2 = sx[a + 1];
                c3 = cR ? sx[a + 2] : 0.f;
            }
            r0q0 = pk2(c0, c1); r0q1 = pk2(c1, c2); r0q2 = pk2(c2, c3);
        }
        {
            int a = r0 * 56 + col;
            float c0 = cL ? sx[a - 1] : 0.f;
            float c1 = sx[a], c2 = sx[a + 1];
            float c3 = cR ? sx[a + 2] : 0.f;
            r1q0 = pk2(c0, c1); r1q1 = pk2(c1, c2); r1q2 = pk2(c2, c3);
        }

#pragma unroll
        for (int j = 0; j < 7; j++) {
            const int rr = r0 + j + 1;
            unsigned long long r2q0, r2q1, r2q2;
            {
                float c0 = 0.f, c1 = 0.f, c2 = 0.f, c3 = 0.f;
                if (rr < 56) {
                    int a = rr * 56 + col;
                    c0 = cL ? sx[a - 1] : 0.f;
                    c1 = sx[a]; c2 = sx[a + 1];
                    c3 = cR ? sx[a + 2] : 0.f;
                }
                r2q0 = pk2(c0, c1); r2q1 = pk2(c1, c2); r2q2 = pk2(c2, c3);
            }
            unsigned long long acc = mul2(r0q0, ww0);
            acc = fma2(r0q1, ww1, acc); acc = fma2(r0q2, ww2, acc);
            acc = fma2(r1q0, ww3, acc); acc = fma2(r1q1, ww4, acc);
            acc = fma2(r1q2, ww5, acc);
            acc = fma2(r2q0, ww6, acc); acc = fma2(r2q1, ww7, acc);
            acc = fma2(r2q2, ww8, acc);
            acc = fma2(acc, ss, tt);
            float2 pr = upk2(acc);
            float z0 = fmaxf(pr.x, 0.f), z1 = fmaxf(pr.y, 0.f);
            lv[j] = make_float2(z0, z1);
            mx = fmaxf(mx, fmaxf(z0, z1));
            r0q0 = r1q0; r0q1 = r1q1; r0q2 = r1q2;
            r1q0 = r2q0; r1q1 = r2q1; r1q2 = r2q2;
        }
    }

    for (int off = 16; off; off >>= 1)
        mx = fmaxf(mx, __shfl_xor_sync(0xffffffffu, mx, off));
    if ((tid & 31) == 0) red[tid >> 5] = mx;
    __syncthreads();
    if (tid == 0) {
        float m = red[0];
#pragma unroll
        for (int i = 1; i < 8; i++) m = fmaxf(m, red[i]);
        s_bmax = m;
        g_keep[slice] = (m >= DW_THR) ? 1 : 0;
    }
    __syncthreads();

    if (s_bmax >= DW_THR && tid < 224) {
        float* yo = g_y + (size_t)slice * 3136 + band * 7 * 56 + 2 * p;
#pragma unroll
        for (int j = 0; j < 7; j++)
            *(float2*)(yo + j * 56) = lv[j];
    }
}

// ---------------------------------------------------------------------------
// Per-batch compaction of kept channels
// ---------------------------------------------------------------------------
__global__ void compact_kernel() {
    const int b = blockIdx.x;
    const int tid = threadIdx.x;              // 128 threads
    __shared__ int wcnt[4];
    const int f = g_keep[b * 128 + tid];
    const unsigned bal = __ballot_sync(0xffffffffu, f);
    const int lane = tid & 31, w = tid >> 5;
    const int pre = __popc(bal & ((1u << lane) - 1u));
    if (lane == 0) wcnt[w] = __popc(bal);
    __syncthreads();
    int off = 0;
#pragma unroll
    for (int i = 0; i < 4; i++) if (i < w) off += wcnt[i];
    if (f) g_idx[b * 128 + off + pre] = tid;
    if (tid == 0) g_cnt[b] = wcnt[0] + wcnt[1] + wcnt[2] + wcnt[3];
}

// ---------------------------------------------------------------------------
// Pointwise conv + BN2 + ReLU + BLOCK-LOCAL prune.
// Block = 32 O x 3136 HW stripe. grid (8, 64) = 512 blocks, 256 threads.
// FAST PATH (cnt <= 32): W staged once; Y double-buffered, ONE sync/chunk.
// General path (cnt > 32): round-12 subtiled logic.
// ---------------------------------------------------------------------------
#define KSUB 32
__global__ __launch_bounds__(256, 4) void pw_kernel(
    const float* __restrict__ pw_w, const float* __restrict__ pw_b,
    const float* __restrict__ g2,  const float* __restrict__ b2,
    const float* __restrict__ m2,  const float* __restrict__ v2,
    float* __restrict__ out)
{
    __shared__ float sWs[KSUB][36];          // [k][o]  32 used + 4 pad
    __shared__ float sYd[2][KSUB][132];      // double-buffered [k][hw]
    __shared__ int   sidx[128];
    __shared__ unsigned char sfail[32];

    const int tid = threadIdx.x;
    const int tx = tid & 31;                 // hw: 32 lanes x 4 floats
    const int ty = tid >> 5;                 // o : 8 warps x 4 o's
    const int ob = blockIdx.x * 32;
    const int b  = blockIdx.y;

    const int cnt  = g_cnt[b];
    const int cnt4 = (cnt + 3) & ~3;
    const int nsub = (cnt4 + KSUB - 1) / KSUB;

    if (tid < 128) sidx[tid] = (tid < cnt) ? g_idx[b * 128 + tid] : -1;
    __syncthreads();

    float sc[4], tc[4], m[4];
    float* orow[4];
#pragma unroll
    for (int r = 0; r < 4; r++) {
        int o = ob + ty * 4 + r;
        sc[r] = g2[o] * rsqrtf(v2[o] + EPSV);
        tc[r] = fmaf(pw_b[o] - m2[o], sc[r], b2[o]);
        m[r] = 0.f;
        orow[r] = out + ((size_t)(b * 256 + o)) * 3136;
    }

    if (nsub <= 1) {
        // ---------- fast path: cnt <= 32, W staged once, Y double-buffered ----
        const int klim = cnt4;
        for (int i = tid; i < klim * 32; i += 256) {
            int lk = i >> 5, oo = i & 31;
            int ch = sidx[lk];
            sWs[lk][oo] = (ch >= 0) ? pw_w[(ob + oo) * 128 + ch] : 0.f;
        }

        for (int it = 0; it < 25; it++) {
            const int hw0 = it * 128;
            const bool full = (it < 24);
            const bool live = full | (tx < 16);
            float (*sY)[132] = sYd[it & 1];

            if (full) {
                for (int i = tid; i < klim * 32; i += 256) {
                    int lk = i >> 5, f4 = i & 31;
                    int ch = sidx[lk];
                    float4 v = make_float4(0.f, 0.f, 0.f, 0.f);
                    if (ch >= 0)
                        v = *(const float4*)(g_y + ((size_t)(b * 128 + ch)) * 3136 + hw0 + f4 * 4);
                    *(float4*)&sY[lk][f4 * 4] = v;
                }
            } else {
                for (int i = tid; i < klim * 16; i += 256) {
                    int lk = i >> 4, f4 = i & 15;
                    int ch = sidx[lk];
                    float4 v = make_float4(0.f, 0.f, 0.f, 0.f);
                    if (ch >= 0)
                        v = *(const float4*)(g_y + ((size_t)(b * 128 + ch)) * 3136 + hw0 + f4 * 4);
                    *(float4*)&sY[lk][f4 * 4] = v;
                }
            }
            __syncthreads();     // the ONLY sync per chunk

            if (live) {
                unsigned long long acc[2][4];
#pragma unroll
                for (int p = 0; p < 2; p++)
#pragma unroll
                    for (int q = 0; q < 4; q++) acc[p][q] = 0ull;

                for (int lk0 = 0; lk0 < klim; lk0 += 4) {
#pragma unroll
                    for (int ku = 0; ku < 4; ku++) {
                        int lk = lk0 + ku;
                        float4 Y = *(const float4*)&sY[lk][tx * 4];
                        float4 Wv = *(const float4*)&sWs[lk][ty * 4];
                        unsigned long long w01 = pk2(Wv.x, Wv.y);
                        unsigned long long w23 = pk2(Wv.z, Wv.w);
                        unsigned long long yx = pk2(Y.x, Y.x), yy = pk2(Y.y, Y.y);
                        unsigned long long yz = pk2(Y.z, Y.z), yw = pk2(Y.w, Y.w);
                        acc[0][0] = fma2(w01, yx, acc[0][0]);
                        acc[0][1] = fma2(w01, yy, acc[0][1]);
                        acc[0][2] = fma2(w01, yz, acc[0][2]);
                        acc[0][3] = fma2(w01, yw, acc[0][3]);
                        acc[1][0] = fma2(w23, yx, acc[1][0]);
                        acc[1][1] = fma2(w23, yy, acc[1][1]);
                        acc[1][2] = fma2(w23, yz, acc[1][2]);
                        acc[1][3] = fma2(w23, yw, acc[1][3]);
                    }
                }

                float z[4][4];
#pragma unroll
                for (int q = 0; q < 4; q++) {
                    float2 a01 = upk2(acc[0][q]);
                    float2 a23 = upk2(acc[1][q]);
                    z[0][q] = fmaxf(fmaf(a01.x, sc[0], tc[0]), 0.f);
                    z[1][q] = fmaxf(fmaf(a01.y, sc[1], tc[1]), 0.f);
                    z[2][q] = fmaxf(fmaf(a23.x, sc[2], tc[2]), 0.f);
                    z[3][q] = fmaxf(fmaf(a23.y, sc[3], tc[3]), 0.f);
                }
#pragma unroll
                for (int r = 0; r < 4; r++) {
                    m[r] = fmaxf(m[r], fmaxf(fmaxf(z[r][0], z[r][1]),
                                             fmaxf(z[r][2], z[r][3])));
                    *(float4*)(orow[r] + hw0 + tx * 4) =
                        make_float4(z[r][0], z[r][1], z[r][2], z[r][3]);
                }
            }
        }
    } else {
        // ---------- general path: cnt > 32 (round-12 logic) -------------------
        float (*sY)[132] = sYd[0];
        for (int it = 0; it < 25; it++) {
            const int hw0 = it * 128;
            const bool full = (it < 24);
            const bool live = full | (tx < 16);

            unsigned long long acc[2][4];
#pragma unroll
            for (int p = 0; p < 2; p++)
#pragma unroll
                for (int q = 0; q < 4; q++) acc[p][q] = 0ull;

            for (int kt = 0; kt < nsub; kt++) {
                const int kbase = kt * KSUB;
                int klim = cnt4 - kbase;
                if (klim > KSUB) klim = KSUB;

                for (int i = tid; i < klim * 32; i += 256) {
                    int lk = i >> 5, oo = i & 31;
                    int ch = sidx[kbase + lk];
                    sWs[lk][oo] = (ch >= 0) ? pw_w[(ob + oo) * 128 + ch] : 0.f;
                }
                for (int i = tid; i < klim * 32; i += 256) {
                    int lk = i >> 5, f4 = i & 31;
                    int ch = sidx[kbase + lk];
                    float4 v = make_float4(0.f, 0.f, 0.f, 0.f);
                    if (ch >= 0 && (full || (f4 < 16)))
                        v = *(const float4*)(g_y + ((size_t)(b * 128 + ch)) * 3136 + hw0 + f4 * 4);
                    *(float4*)&sY[lk][f4 * 4] = v;
                }
                __syncthreads();

                if (live) {
                    for (int lk0 = 0; lk0 < klim; lk0 += 4) {
#pragma unroll
                        for (int ku = 0; ku < 4; ku++) {
                            int lk = lk0 + ku;
                            float4 Y = *(const float4*)&sY[lk][tx * 4];
                            float4 Wv = *(const float4*)&sWs[lk][ty * 4];
                            unsigned long long w01 = pk2(Wv.x, Wv.y);
                            unsigned long long w23 = pk2(Wv.z, Wv.w);
                            unsigned long long yx = pk2(Y.x, Y.x), yy = pk2(Y.y, Y.y);
                            unsigned long long yz = pk2(Y.z, Y.z), yw = pk2(Y.w, Y.w);
                            acc[0][0] = fma2(w01, yx, acc[0][0]);
                            acc[0][1] = fma2(w01, yy, acc[0][1]);
                            acc[0][2] = fma2(w01, yz, acc[0][2]);
                            acc[0][3] = fma2(w01, yw, acc[0][3]);
                            acc[1][0] = fma2(w23, yx, acc[1][0]);
                            acc[1][1] = fma2(w23, yy, acc[1][1]);
                            acc[1][2] = fma2(w23, yz, acc[1][2]);
                            acc[1][3] = fma2(w23, yw, acc[1][3]);
                        }
                    }
                }
                __syncthreads();
            }

            if (live) {
                float z[4][4];
#pragma unroll
                for (int q = 0; q < 4; q++) {
                    float2 a01 = upk2(acc[0][q]);
                    float2 a23 = upk2(acc[1][q]);
                    z[0][q] = fmaxf(fmaf(a01.x, sc[0], tc[0]), 0.f);
                    z[1][q] = fmaxf(fmaf(a01.y, sc[1], tc[1]), 0.f);
                    z[2][q] = fmaxf(fmaf(a23.x, sc[2], tc[2]), 0.f);
                    z[3][q] = fmaxf(fmaf(a23.y, sc[3], tc[3]), 0.f);
                }
#pragma unroll
                for (int r = 0; r < 4; r++) {
                    m[r] = fmaxf(m[r], fmaxf(fmaxf(z[r][0], z[r][1]),
                                             fmaxf(z[r][2], z[r][3])));
                    *(float4*)(orow[r] + hw0 + tx * 4) =
                        make_float4(z[r][0], z[r][1], z[r][2], z[r][3]);
                }
            }
        }
    }

    // per-o max over 32 lanes
#pragma unroll
    for (int r = 0; r < 4; r++) {
#pragma unroll
        for (int off = 1; off < 32; off <<= 1)
            m[r] = fmaxf(m[r], __shfl_xor_sync(0xffffffffu, m[r], off));
    }
    if (tx == 0) {
#pragma unroll
        for (int r = 0; r < 4; r++)
            sfail[ty * 4 + r] = (m[r] < PW_THR) ? 1 : 0;
    }
    __syncthreads();

    // block-local prune: zero failing rows
    const float4 zz = make_float4(0.f, 0.f, 0.f, 0.f);
    for (int oo = 0; oo < 32; oo++) {
        if (sfail[oo]) {
            float4* p4 = (float4*)(out + ((size_t)(b * 256 + ob + oo)) * 3136);
            for (int i = tid; i < 784; i += 256) p4[i] = zz;
        }
    }
}

// ---------------------------------------------------------------------------
extern "C" void kernel_launch(void* const* d_in, const int* in_sizes, int n_in,
                              void* d_out, int out_size)
{
    const float* x    = (const float*)d_in[0];
    const float* dw_w = (const float*)d_in[1];
    const float* dw_b = (const float*)d_in[2];
    const float* g1   = (const float*)d_in[3];
    const float* b1   = (const float*)d_in[4];
    const float* m1   = (const float*)d_in[5];
    const float* v1   = (const float*)d_in[6];
    const float* pw_w = (const float*)d_in[7];
    const float* pw_b = (const float*)d_in[8];
    const float* g2   = (const float*)d_in[9];
    const float* b2   = (const float*)d_in[10];
    const float* m2   = (const float*)d_in[11];
    const float* v2   = (const float*)d_in[12];
    float* out = (float*)d_out;

    dw_kernel<<<64 * 128, 256>>>(x, dw_w, dw_b, g1, b1, m1, v1);
    compact_kernel<<<64, 128>>>();
    pw_kernel<<<dim3(8, 64), 256>>>(pw_w, pw_b, g2, b2, m2, v2, out);
}

// round 15
// speedup vs baseline: 1.1578x; 1.0301x over previous
#include <cuda_runtime.h>

#define EPSV   1e-5f
#define DW_THR 4.0f
#define PW_THR 0.001f

// Shapes: B=64, C=128, O=256, H=W=56, HW=3136
__device__ float g_y[64 * 128 * 3136];   // pruned depthwise output [B,C,HW]
__device__ int   g_keep[64 * 128];       // per-(b,c) keep flag
__device__ int   g_idx[64 * 128];        // per-b compacted kept-channel list
__device__ int   g_cnt[64];              // per-b kept count

// ---------------------------------------------------------------------------
// packed fp32x2 helpers (Blackwell FFMA2)
// ---------------------------------------------------------------------------
__device__ __forceinline__ unsigned long long fma2(unsigned long long a,
                                                   unsigned long long b,
                                                   unsigned long long c) {
    unsigned long long d;
    asm("fma.rn.f32x2 %0, %1, %2, %3;" : "=l"(d) : "l"(a), "l"(b), "l"(c));
    return d;
}
__device__ __forceinline__ unsigned long long mul2(unsigned long long a,
                                                   unsigned long long b) {
    unsigned long long d;
    asm("mul.rn.f32x2 %0, %1, %2;" : "=l"(d) : "l"(a), "l"(b));
    return d;
}
__device__ __forceinline__ unsigned long long pk2(float lo, float hi) {
    unsigned long long d;
    asm("mov.b64 %0, {%1, %2};" : "=l"(d) : "f"(lo), "f"(hi));
    return d;
}
__device__ __forceinline__ float2 upk2(unsigned long long v) {
    float2 r;
    asm("mov.b64 {%0, %1}, %2;" : "=f"(r.x), "=f"(r.y) : "l"(v));
    return r;
}

// ---------------------------------------------------------------------------
// Depthwise 3x3 + bias + BN1 + ReLU + per-(b,c) prune.
// (round-12 version, measured 38.2-38.7us, occ ~93%)
// ---------------------------------------------------------------------------
__global__ __launch_bounds__(256) void dw_kernel(
    const float* __restrict__ x,
    const float* __restrict__ dw_w, const float* __restrict__ dw_b,
    const float* __restrict__ g1,  const float* __restrict__ b1,
    const float* __restrict__ m1,  const float* __restrict__ v1)
{
    __shared__ float sx[3136];
    __shared__ float red[8];
    __shared__ float s_bmax;

    const int slice = blockIdx.x;          // b*128 + c
    const int c = slice & 127;
    const float* xs = x + (size_t)slice * 3136;

    const unsigned long long ww0 = pk2(dw_w[c*9+0], dw_w[c*9+0]);
    const unsigned long long ww1 = pk2(dw_w[c*9+1], dw_w[c*9+1]);
    const unsigned long long ww2 = pk2(dw_w[c*9+2], dw_w[c*9+2]);
    const unsigned long long ww3 = pk2(dw_w[c*9+3], dw_w[c*9+3]);
    const unsigned long long ww4 = pk2(dw_w[c*9+4], dw_w[c*9+4]);
    const unsigned long long ww5 = pk2(dw_w[c*9+5], dw_w[c*9+5]);
    const unsigned long long ww6 = pk2(dw_w[c*9+6], dw_w[c*9+6]);
    const unsigned long long ww7 = pk2(dw_w[c*9+7], dw_w[c*9+7]);
    const unsigned long long ww8 = pk2(dw_w[c*9+8], dw_w[c*9+8]);
    const float s = g1[c] * rsqrtf(v1[c] + EPSV);
    const float t = fmaf(dw_b[c] - m1[c], s, b1[c]);
    const unsigned long long ss = pk2(s, s);
    const unsigned long long tt = pk2(t, t);

    const int tid = threadIdx.x;

    {   // stage slice: 784 coalesced float4
        const float4* x4 = (const float4*)xs;
        float4* s4 = (float4*)sx;
        for (int i = tid; i < 784; i += 256) s4[i] = x4[i];
    }
    __syncthreads();

    float2 lv[7];
    float mx = 0.f;
    int p = 0, band = 0;
    if (tid < 224) {
        band = tid / 28;               // 0..7
        p    = tid - band * 28;        // col pair -> cols 2p, 2p+1
        const bool cL = (p > 0), cR = (p < 27);
        const int col = 2 * p;
        const int r0  = band * 7;

        unsigned long long r0q0, r0q1, r0q2, r1q0, r1q1, r1q2;
        {
            float c0 = 0.f, c1 = 0.f, c2 = 0.f, c3 = 0.f;
            if (r0 > 0) {
                int a = (r0 - 1) * 56 + col;
                c0 = cL ? sx[a - 1] : 0.f;
                c1 = sx[a]; c2 = sx[a + 1];
                c3 = cR ? sx[a + 2] : 0.f;
            }
            r0q0 = pk2(c0, c1); r0q1 = pk2(c1, c2); r0q2 = pk2(c2, c3);
        }
        {
            int a = r0 * 56 + col;
            float c0 = cL ? sx[a - 1] : 0.f;
            float c1 = sx[a], c2 = sx[a + 1];
            float c3 = cR ? sx[a + 2] : 0.f;
            r1q0 = pk2(c0, c1); r1q1 = pk2(c1, c2); r1q2 = pk2(c2, c3);
        }

#pragma unroll
        for (int j = 0; j < 7; j++) {
            const int rr = r0 + j + 1;
            unsigned long long r2q0, r2q1, r2q2;
            {
                float c0 = 0.f, c1 = 0.f, c2 = 0.f, c3 = 0.f;
                if (rr < 56) {
                    int a = rr * 56 + col;
                    c0 = cL ? sx[a - 1] : 0.f;
                    c1 = sx[a]; c2 = sx[a + 1];
                    c3 = cR ? sx[a + 2] : 0.f;
                }
                r2q0 = pk2(c0, c1); r2q1 = pk2(c1, c2); r2q2 = pk2(c2, c3);
            }
            unsigned long long acc = mul2(r0q0, ww0);
            acc = fma2(r0q1, ww1, acc); acc = fma2(r0q2, ww2, acc);
            acc = fma2(r1q0, ww3, acc); acc = fma2(r1q1, ww4, acc);
            acc = fma2(r1q2, ww5, acc);
            acc = fma2(r2q0, ww6, acc); acc = fma2(r2q1, ww7, acc);
            acc = fma2(r2q2, ww8, acc);
            acc = fma2(acc, ss, tt);
            float2 pr = upk2(acc);
            float z0 = fmaxf(pr.x, 0.f), z1 = fmaxf(pr.y, 0.f);
            lv[j] = make_float2(z0, z1);
            mx = fmaxf(mx, fmaxf(z0, z1));
            r0q0 = r1q0; r0q1 = r1q1; r0q2 = r1q2;
            r1q0 = r2q0; r1q1 = r2q1; r1q2 = r2q2;
        }
    }

    for (int off = 16; off; off >>= 1)
        mx = fmaxf(mx, __shfl_xor_sync(0xffffffffu, mx, off));
    if ((tid & 31) == 0) red[tid >> 5] = mx;
    __syncthreads();
    if (tid == 0) {
        float m = red[0];
#pragma unroll
        for (int i = 1; i < 8; i++) m = fmaxf(m, red[i]);
        s_bmax = m;
        g_keep[slice] = (m >= DW_THR) ? 1 : 0;
    }
    __syncthreads();

    if (s_bmax >= DW_THR && tid < 224) {
        float* yo = g_y + (size_t)slice * 3136 + band * 7 * 56 + 2 * p;
#pragma unroll
        for (int j = 0; j < 7; j++)
            *(float2*)(yo + j * 56) = lv[j];
    }
}

// ---------------------------------------------------------------------------
// Per-batch compaction of kept channels
// ---------------------------------------------------------------------------
__global__ void compact_kernel() {
    const int b = blockIdx.x;
    const int tid = threadIdx.x;              // 128 threads
    __shared__ int wcnt[4];
    const int f = g_keep[b * 128 + tid];
    const unsigned bal = __ballot_sync(0xffffffffu, f);
    const int lane = tid & 31, w = tid >> 5;
    const int pre = __popc(bal & ((1u << lane) - 1u));
    if (lane == 0) wcnt[w] = __popc(bal);
    __syncthreads();
    int off = 0;
#pragma unroll
    for (int i = 0; i < 4; i++) if (i < w) off += wcnt[i];
    if (f) g_idx[b * 128 + off + pre] = tid;
    if (tid == 0) g_cnt[b] = wcnt[0] + wcnt[1] + wcnt[2] + wcnt[3];
}

// ---------------------------------------------------------------------------
// Pointwise conv + BN2 + ReLU + BLOCK-LOCAL prune.
// Block = 32 O x 3136 HW stripe. grid (8, 64) = 512 blocks, 256 threads.
// FAST PATH (cnt <= 32): W staged once in DUPLICATED layout (LDS.128 yields
// (w,w) pairs, no MOVs); Y register-prefetched one chunk ahead so the global
// load overlaps compute; ONE sync/chunk. General path for cnt > 32.
// ---------------------------------------------------------------------------
#define KSUB 32
__global__ __launch_bounds__(256, 4) void pw_kernel(
    const float* __restrict__ pw_w, const float* __restrict__ pw_b,
    const float* __restrict__ g2,  const float* __restrict__ b2,
    const float* __restrict__ m2,  const float* __restrict__ v2,
    float* __restrict__ out)
{
    __shared__ __align__(16) float sWd[KSUB][72];     // [k][2*o] duplicated W
    __shared__ __align__(16) float sYd[2][KSUB][132]; // double-buffered [k][hw]
    __shared__ int   sidx[128];
    __shared__ unsigned char sfail[32];

    const int tid = threadIdx.x;
    const int tx = tid & 31;                 // hw: 32 lanes x 4 floats
    const int ty = tid >> 5;                 // o : 8 warps x 4 o's
    const int ob = blockIdx.x * 32;
    const int b  = blockIdx.y;

    const int cnt  = g_cnt[b];
    const int cnt4 = (cnt + 3) & ~3;
    const int nsub = (cnt4 + KSUB - 1) / KSUB;

    if (tid < 128) sidx[tid] = (tid < cnt) ? g_idx[b * 128 + tid] : -1;
    __syncthreads();

    float sc[4], tc[4], m[4];
#pragma unroll
    for (int r = 0; r < 4; r++) {
        int o = ob + ty * 4 + r;
        sc[r] = g2[o] * rsqrtf(v2[o] + EPSV);
        tc[r] = fmaf(pw_b[o] - m2[o], sc[r], b2[o]);
        m[r] = 0.f;
    }
    const size_t outbase = ((size_t)(b * 256 + ob + ty * 4)) * 3136;

    if (nsub <= 1) {
        // ============ fast path: cnt <= 32 ============
        const int klim = cnt4;
        const int nelem = klim * 32;               // f4 elements per chunk

        // stage W once, duplicated
        for (int i = tid; i < klim * 32; i += 256) {
            int lk = i >> 5, oo = i & 31;
            int ch = sidx[lk];
            float w = (ch >= 0) ? pw_w[(ob + oo) * 128 + ch] : 0.f;
            sWd[lk][2 * oo]     = w;
            sWd[lk][2 * oo + 1] = w;
        }

        // prefetch chunk 0 into registers
        float4 yreg[4];
#pragma unroll
        for (int u = 0; u < 4; u++) {
            int i = u * 256 + tid;
            float4 v = make_float4(0.f, 0.f, 0.f, 0.f);
            if (i < nelem) {
                int lk = i >> 5, f4 = i & 31;
                int ch = sidx[lk];
                if (ch >= 0)
                    v = *(const float4*)(g_y + ((size_t)(b * 128 + ch)) * 3136 + f4 * 4);
            }
            yreg[u] = v;
        }

        for (int it = 0; it < 25; it++) {
            const int hw0 = it * 128;
            const bool live = (it < 24) | (tx < 16);
            float (*sY)[132] = sYd[it & 1];

            // commit prefetched Y to smem
#pragma unroll
            for (int u = 0; u < 4; u++) {
                int i = u * 256 + tid;
                if (i < nelem) {
                    int lk = i >> 5, f4 = i & 31;
                    *(float4*)&sY[lk][f4 * 4] = yreg[u];
                }
            }
            __syncthreads();                 // the ONLY sync per chunk

            // issue next chunk's loads (overlap with compute below)
            if (it < 24) {
                const int hwn = hw0 + 128;
#pragma unroll
                for (int u = 0; u < 4; u++) {
                    int i = u * 256 + tid;
                    float4 v = make_float4(0.f, 0.f, 0.f, 0.f);
                    if (i < nelem) {
                        int lk = i >> 5, f4 = i & 31;
                        int ch = sidx[lk];
                        int hw = hwn + f4 * 4;
                        if (ch >= 0 && hw < 3136)
                            v = *(const float4*)(g_y + ((size_t)(b * 128 + ch)) * 3136 + hw);
                    }
                    yreg[u] = v;
                }
            }

            // compute: acc[o][hw-pair], W pairs native from duplicated smem
            unsigned long long acc[4][2];
#pragma unroll
            for (int r = 0; r < 4; r++) { acc[r][0] = 0ull; acc[r][1] = 0ull; }

            for (int lk0 = 0; lk0 < klim; lk0 += 4) {
#pragma unroll
                for (int ku = 0; ku < 4; ku++) {
                    int lk = lk0 + ku;
                    ulonglong2 Yp  = *(const ulonglong2*)&sY[lk][tx * 4];
                    ulonglong2 W01 = *(const ulonglong2*)&sWd[lk][ty * 8];
                    ulonglong2 W23 = *(const ulonglong2*)&sWd[lk][ty * 8 + 4];
                    acc[0][0] = fma2(W01.x, Yp.x, acc[0][0]);
                    acc[0][1] = fma2(W01.x, Yp.y, acc[0][1]);
                    acc[1][0] = fma2(W01.y, Yp.x, acc[1][0]);
                    acc[1][1] = fma2(W01.y, Yp.y, acc[1][1]);
                    acc[2][0] = fma2(W23.x, Yp.x, acc[2][0]);
                    acc[2][1] = fma2(W23.x, Yp.y, acc[2][1]);
                    acc[3][0] = fma2(W23.y, Yp.x, acc[3][0]);
                    acc[3][1] = fma2(W23.y, Yp.y, acc[3][1]);
                }
            }

            if (live) {
#pragma unroll
                for (int r = 0; r < 4; r++) {
                    float2 a01 = upk2(acc[r][0]);
                    float2 a23 = upk2(acc[r][1]);
                    float z0 = fmaxf(fmaf(a01.x, sc[r], tc[r]), 0.f);
                    float z1 = fmaxf(fmaf(a01.y, sc[r], tc[r]), 0.f);
                    float z2 = fmaxf(fmaf(a23.x, sc[r], tc[r]), 0.f);
                    float z3 = fmaxf(fmaf(a23.y, sc[r], tc[r]), 0.f);
                    m[r] = fmaxf(m[r], fmaxf(fmaxf(z0, z1), fmaxf(z2, z3)));
                    *(float4*)(out + outbase + (size_t)r * 3136 + hw0 + tx * 4) =
                        make_float4(z0, z1, z2, z3);
                }
            }
        }
    } else {
        // ============ general path: cnt > 32 (subtiled, 2 syncs/subtile) ======
        float (*sY)[132] = sYd[0];
        for (int it = 0; it < 25; it++) {
            const int hw0 = it * 128;
            const bool full = (it < 24);
            const bool live = full | (tx < 16);

            unsigned long long acc[4][2];
#pragma unroll
            for (int r = 0; r < 4; r++) { acc[r][0] = 0ull; acc[r][1] = 0ull; }

            for (int kt = 0; kt < nsub; kt++) {
                const int kbase = kt * KSUB;
                int klim = cnt4 - kbase;
                if (klim > KSUB) klim = KSUB;

                for (int i = tid; i < klim * 32; i += 256) {
                    int lk = i >> 5, oo = i & 31;
                    int ch = sidx[kbase + lk];
                    float w = (ch >= 0) ? pw_w[(ob + oo) * 128 + ch] : 0.f;
                    sWd[lk][2 * oo]     = w;
                    sWd[lk][2 * oo + 1] = w;
                }
                for (int i = tid; i < klim * 32; i += 256) {
                    int lk = i >> 5, f4 = i & 31;
                    int ch = sidx[kbase + lk];
                    int hw = hw0 + f4 * 4;
                    float4 v = make_float4(0.f, 0.f, 0.f, 0.f);
                    if (ch >= 0 && hw < 3136)
                        v = *(const float4*)(g_y + ((size_t)(b * 128 + ch)) * 3136 + hw);
                    *(float4*)&sY[lk][f4 * 4] = v;
                }
                __syncthreads();

                for (int lk0 = 0; lk0 < klim; lk0 += 4) {
#pragma unroll
                    for (int ku = 0; ku < 4; ku++) {
                        int lk = lk0 + ku;
                        ulonglong2 Yp  = *(const ulonglong2*)&sY[lk][tx * 4];
                        ulonglong2 W01 = *(const ulonglong2*)&sWd[lk][ty * 8];
                        ulonglong2 W23 = *(const ulonglong2*)&sWd[lk][ty * 8 + 4];
                        acc[0][0] = fma2(W01.x, Yp.x, acc[0][0]);
                        acc[0][1] = fma2(W01.x, Yp.y, acc[0][1]);
                        acc[1][0] = fma2(W01.y, Yp.x, acc[1][0]);
                        acc[1][1] = fma2(W01.y, Yp.y, acc[1][1]);
                        acc[2][0] = fma2(W23.x, Yp.x, acc[2][0]);
                        acc[2][1] = fma2(W23.x, Yp.y, acc[2][1]);
                        acc[3][0] = fma2(W23.y, Yp.x, acc[3][0]);
                        acc[3][1] = fma2(W23.y, Yp.y, acc[3][1]);
                    }
                }
                __syncthreads();
            }

            if (live) {
#pragma unroll
                for (int r = 0; r < 4; r++) {
                    float2 a01 = upk2(acc[r][0]);
                    float2 a23 = upk2(acc[r][1]);
                    float z0 = fmaxf(fmaf(a01.x, sc[r], tc[r]), 0.f);
                    float z1 = fmaxf(fmaf(a01.y, sc[r], tc[r]), 0.f);
                    float z2 = fmaxf(fmaf(a23.x, sc[r], tc[r]), 0.f);
                    float z3 = fmaxf(fmaf(a23.y, sc[r], tc[r]), 0.f);
                    m[r] = fmaxf(m[r], fmaxf(fmaxf(z0, z1), fmaxf(z2, z3)));
                    *(float4*)(out + outbase + (size_t)r * 3136 + hw0 + tx * 4) =
                        make_float4(z0, z1, z2, z3);
                }
            }
        }
    }

    // per-o max over 32 lanes
#pragma unroll
    for (int r = 0; r < 4; r++) {
#pragma unroll
        for (int off = 1; off < 32; off <<= 1)
            m[r] = fmaxf(m[r], __shfl_xor_sync(0xffffffffu, m[r], off));
    }
    if (tx == 0) {
#pragma unroll
        for (int r = 0; r < 4; r++)
            sfail[ty * 4 + r] = (m[r] < PW_THR) ? 1 : 0;
    }
    __syncthreads();

    // block-local prune: zero failing rows
    const float4 zz = make_float4(0.f, 0.f, 0.f, 0.f);
    for (int oo = 0; oo < 32; oo++) {
        if (sfail[oo]) {
            float4* p4 = (float4*)(out + ((size_t)(b * 256 + ob + oo)) * 3136);
            for (int i = tid; i < 784; i += 256) p4[i] = zz;
        }
    }
}

// ---------------------------------------------------------------------------
extern "C" void kernel_launch(void* const* d_in, const int* in_sizes, int n_in,
                              void* d_out, int out_size)
{
    const float* x    = (const float*)d_in[0];
    const float* dw_w = (const float*)d_in[1];
    const float* dw_b = (const float*)d_in[2];
    const float* g1   = (const float*)d_in[3];
    const float* b1   = (const float*)d_in[4];
    const float* m1   = (const float*)d_in[5];
    const float* v1   = (const float*)d_in[6];
    const float* pw_w = (const float*)d_in[7];
    const float* pw_b = (const float*)d_in[8];
    const float* g2   = (const float*)d_in[9];
    const float* b2   = (const float*)d_in[10];
    const float* m2   = (const float*)d_in[11];
    const float* v2   = (const float*)d_in[12];
    float* out = (float*)d_out;

    dw_kernel<<<64 * 128, 256>>>(x, dw_w, dw_b, g1, b1, m1, v1);
    compact_kernel<<<64, 128>>>();
    pw_kernel<<<dim3(8, 64), 256>>>(pw_w, pw_b, g2, b2, m2, v2, out);
}